// round 5
// baseline (speedup 1.0000x reference)
#include <cuda_runtime.h>
#include <cuda_bf16.h>

// Degenerate BiLSTM: h=c=0 => only emb[:,S-1] (fwd) and emb[:,0] (bwd) matter;
// f-gate dead; Whf/Whb unused.  B=128, S=2048, EMB=128, HID=256, OUT=32.
//
// One kernel, 128 blocks (32 h-chunks x 4 batch-groups) x 512 threads.
// Warp = (h, k-half); lanes = 32 batches (W LDGs are lane-uniform broadcasts).
// k-halves combine via conflict-free smem. hy stored transposed g_hy[h][b].
// Last block per batch-group (monotonic atomic counter) computes the head
// (Why staged in padded smem) + 32-wide log-softmax.

#define NB_B   128
#define NB_S   2048
#define NB_EMB 128
#define NB_HID 256
#define NB_OUT 32

__device__ float g_hy[NB_HID * NB_B];   // [h][b], coalesced stores
__device__ unsigned int g_cnt[4];        // monotonic, 32 incr per bg per launch

__device__ __forceinline__ float fsigm(float x) {
    return __fdividef(1.0f, 1.0f + __expf(-x));
}
__device__ __forceinline__ float ftanh(float x) {
    float r; asm("tanh.approx.f32 %0, %1;" : "=f"(r) : "f"(x)); return r;
}

__global__ void __launch_bounds__(512, 1) bilstm_fused_kernel(
    const int*   __restrict__ inputs,   // [B, S]
    const float* __restrict__ weight,   // [VOCAB, EMB]
    const float* __restrict__ Wxf,      // [1024, 128]
    const float* __restrict__ bxf,
    const float* __restrict__ bhf,
    const float* __restrict__ Wxb,
    const float* __restrict__ bxb,
    const float* __restrict__ bhb,
    const float* __restrict__ Why,      // [32, 256]
    const float* __restrict__ by,       // [32]
    float*       __restrict__ out)      // [B, 32]
{
    // xs[(dir*128+e)*33 + lb] : 8448 floats (33 KB). Tail reuses it as
    // Why_s[k*33+o] : 8448 floats. red: k-half partials, CF (stride 33).
    __shared__ float xs[2 * NB_EMB * 33];
    __shared__ float red[8 * 6 * 33];
    __shared__ int   tok_s[64];
    __shared__ int   isLast;

    const int tid    = threadIdx.x;
    const int hc     = blockIdx.x & 31;
    const int bg     = blockIdx.x >> 5;
    const int h_base = hc * 8;
    const int b_base = bg * 32;

    if (tid < 64) {
        const int dir = tid >> 5;
        const int lb  = tid & 31;
        tok_s[tid] = inputs[(b_base + lb) * NB_S + (dir ? 0 : (NB_S - 1))];
    }
    __syncthreads();

    // Gather embeddings transposed (LDG coalesced over e, STS conflict-free).
    #pragma unroll
    for (int it = 0; it < 16; it++) {
        const int idx = tid + it * 512;
        const int dir = idx >> 12;
        const int lb  = (idx >> 7) & 31;
        const int e   = idx & 127;
        const int tok = tok_s[dir * 32 + lb];
        xs[(dir * NB_EMB + e) * 33 + lb] = weight[tok * NB_EMB + e];
    }

    const int w  = tid >> 5;       // warp 0..15
    const int lb = tid & 31;       // lane = local batch
    const int kh = w >> 3;         // k-half
    const int hl = w & 7;          // local h
    const int h  = h_base + hl;

    // Hoist bias sums (warp-uniform LDGs) to hide latency under the GEMV.
    const float bif = bxf[h]       + bhf[h];
    const float bgf = bxf[512 + h] + bhf[512 + h];
    const float bof = bxf[768 + h] + bhf[768 + h];
    const float bib = bxb[h]       + bhb[h];
    const float bgb = bxb[512 + h] + bhb[512 + h];
    const float bob = bxb[768 + h] + bhb[768 + h];

    __syncthreads();   // xs ready

    const float* xf = xs + (kh * 64) * 33 + lb;
    const float* xb = xs + (NB_EMB + kh * 64) * 33 + lb;

    const int k0 = kh * 16;   // float4 offset into the 32-chunk row
    const float4* wif = (const float4*)(Wxf + (h)       * NB_EMB) + k0;
    const float4* wgf = (const float4*)(Wxf + (512 + h) * NB_EMB) + k0;
    const float4* wof = (const float4*)(Wxf + (768 + h) * NB_EMB) + k0;
    const float4* wib = (const float4*)(Wxb + (h)       * NB_EMB) + k0;
    const float4* wgb = (const float4*)(Wxb + (512 + h) * NB_EMB) + k0;
    const float4* wob = (const float4*)(Wxb + (768 + h) * NB_EMB) + k0;

    float aif = 0.f, agf = 0.f, aof = 0.f;
    float aib = 0.f, agb = 0.f, aob = 0.f;

    #pragma unroll 4
    for (int k4 = 0; k4 < 16; k4++) {
        const int e = k4 * 4;
        const float a0 = xf[(e + 0) * 33], a1 = xf[(e + 1) * 33];
        const float a2 = xf[(e + 2) * 33], a3 = xf[(e + 3) * 33];
        const float c0 = xb[(e + 0) * 33], c1 = xb[(e + 1) * 33];
        const float c2 = xb[(e + 2) * 33], c3 = xb[(e + 3) * 33];
        float4 v;
        v = wif[k4];
        aif = fmaf(v.x, a0, fmaf(v.y, a1, fmaf(v.z, a2, fmaf(v.w, a3, aif))));
        v = wgf[k4];
        agf = fmaf(v.x, a0, fmaf(v.y, a1, fmaf(v.z, a2, fmaf(v.w, a3, agf))));
        v = wof[k4];
        aof = fmaf(v.x, a0, fmaf(v.y, a1, fmaf(v.z, a2, fmaf(v.w, a3, aof))));
        v = wib[k4];
        aib = fmaf(v.x, c0, fmaf(v.y, c1, fmaf(v.z, c2, fmaf(v.w, c3, aib))));
        v = wgb[k4];
        agb = fmaf(v.x, c0, fmaf(v.y, c1, fmaf(v.z, c2, fmaf(v.w, c3, agb))));
        v = wob[k4];
        aob = fmaf(v.x, c0, fmaf(v.y, c1, fmaf(v.z, c2, fmaf(v.w, c3, aob))));
    }

    // Combine k-halves: warps 8-15 store partials, warps 0-7 finish.
    __syncthreads();   // xs reads done (also fences red reuse)
    if (kh == 1) {
        red[(hl * 6 + 0) * 33 + lb] = aif;
        red[(hl * 6 + 1) * 33 + lb] = agf;
        red[(hl * 6 + 2) * 33 + lb] = aof;
        red[(hl * 6 + 3) * 33 + lb] = aib;
        red[(hl * 6 + 4) * 33 + lb] = agb;
        red[(hl * 6 + 5) * 33 + lb] = aob;
    }
    __syncthreads();

    if (kh == 0) {
        const float gif = aif + red[(hl * 6 + 0) * 33 + lb] + bif;
        const float ggf = agf + red[(hl * 6 + 1) * 33 + lb] + bgf;
        const float gof = aof + red[(hl * 6 + 2) * 33 + lb] + bof;
        const float gib = aib + red[(hl * 6 + 3) * 33 + lb] + bib;
        const float ggb = agb + red[(hl * 6 + 4) * 33 + lb] + bgb;
        const float gob = aob + red[(hl * 6 + 5) * 33 + lb] + bob;

        const float hyv = fsigm(gof) * ftanh(fsigm(gif) * ftanh(ggf))
                        + fsigm(gob) * ftanh(fsigm(gib) * ftanh(ggb));
        g_hy[h * NB_B + b_base + lb] = hyv;   // coalesced
    }

    // ---- election: last block of this batch-group runs the head ----
    __threadfence();
    __syncthreads();
    if (tid == 0) {
        const unsigned int old = atomicAdd(&g_cnt[bg], 1u);
        isLast = ((old & 31u) == 31u);
    }
    __syncthreads();
    if (!isLast) return;
    __threadfence();

    // Stage Why transposed+padded: Why_s[k*33+o]. LDG coalesced, STS CF.
    float* Why_s = xs;
    #pragma unroll
    for (int it = 0; it < 16; it++) {
        const int idx = tid + it * 512;     // idx = o*256 + k
        const int o = idx >> 8;
        const int k = idx & 255;
        Why_s[k * 33 + o] = Why[idx];
    }
    __syncthreads();

    // Head: warp handles 2 batches, lane = output o. hy reads are
    // lane-uniform broadcasts; 4 partial accs for MLP.
    const int o  = tid & 31;
    const int wb = tid >> 5;
    const float bias = by[o];

    #pragma unroll
    for (int rep = 0; rep < 2; rep++) {
        const int b  = wb * 2 + rep;
        const float* hyp = g_hy + b_base + b;   // hyp[k*128]
        float a0 = 0.f, a1 = 0.f, a2 = 0.f, a3 = 0.f;
        #pragma unroll 4
        for (int k = 0; k < NB_HID; k += 4) {
            a0 = fmaf(__ldcg(hyp + (k + 0) * NB_B), Why_s[(k + 0) * 33 + o], a0);
            a1 = fmaf(__ldcg(hyp + (k + 1) * NB_B), Why_s[(k + 1) * 33 + o], a1);
            a2 = fmaf(__ldcg(hyp + (k + 2) * NB_B), Why_s[(k + 2) * 33 + o], a2);
            a3 = fmaf(__ldcg(hyp + (k + 3) * NB_B), Why_s[(k + 3) * 33 + o], a3);
        }
        const float acc = bias + ((a0 + a1) + (a2 + a3));

        float mx = acc;
        #pragma unroll
        for (int off = 16; off; off >>= 1)
            mx = fmaxf(mx, __shfl_xor_sync(0xffffffffu, mx, off));
        float s = __expf(acc - mx);
        #pragma unroll
        for (int off = 16; off; off >>= 1)
            s += __shfl_xor_sync(0xffffffffu, s, off);

        out[(b_base + b) * NB_OUT + o] = acc - mx - __logf(s);
    }
}

// Inputs in metadata order:
// 0 inputs(int32) 1 weight 2 Wxf 3 bxf 4 Whf(unused) 5 bhf
// 6 Wxb 7 bxb 8 Whb(unused) 9 bhb 10 Why 11 by
extern "C" void kernel_launch(void* const* d_in, const int* in_sizes, int n_in,
                              void* d_out, int out_size)
{
    const int*   inputs = (const int*)  d_in[0];
    const float* weight = (const float*)d_in[1];
    const float* Wxf    = (const float*)d_in[2];
    const float* bxf    = (const float*)d_in[3];
    const float* bhf    = (const float*)d_in[5];
    const float* Wxb    = (const float*)d_in[6];
    const float* bxb    = (const float*)d_in[7];
    const float* bhb    = (const float*)d_in[9];
    const float* Why    = (const float*)d_in[10];
    const float* by     = (const float*)d_in[11];
    float*       out    = (float*)d_out;

    bilstm_fused_kernel<<<128, 512>>>(inputs, weight, Wxf, bxf, bhf,
                                      Wxb, bxb, bhb, Why, by, out);
}

// round 6
// speedup vs baseline: 2.0024x; 2.0024x over previous
#include <cuda_runtime.h>
#include <cstdint>

// Degenerate BiLSTM: h=c=0 => only emb[:,S-1] (fwd) and emb[:,0] (bwd) matter;
// f-gate dead; Whf/Whb unused.  B=128, S=2048, EMB=128, HID=256, OUT=32.
//
// Grid 160 = 128 workers (32 h-chunks x 4 batch-groups) + 32 head blocks.
// Worker: W tile via cp.async.bulk -> smem; x gathered transposed (f32x2 pairs);
// GEMV with fma.rn.f32x2, 2 h per thread; hy -> g_hy[h][b]; release + wcnt++.
// Head (4 bg x 8 sub-batch): stages Why during worker phase, epoch-safe
// spin-wait on wcnt, then 4-batch head GEMV + 32-wide log-softmax.

#define NB_B   128
#define NB_S   2048
#define NB_EMB 128
#define NB_HID 256
#define NB_OUT 32

__device__ unsigned int g_wcnt[4];            // +32 per launch per bg (workers)
__device__ unsigned int g_hcnt[4];            // +8  per launch per bg (heads)
__device__ float        g_hy[NB_HID * NB_B];  // [h][b]

// dynamic smem byte offsets
#define SM_XS2   0              // worker: xs2 8448 floats / head: Why_s
#define SM_WSM   33792          // worker: W tile 24576 B
#define SM_HYS   33792          // head: hy_s 1024 floats
#define SM_RED2  (33792+4096)   // head: 4*33 floats
#define SM_RED   58368          // worker: 8*33 floats
#define SM_TOK   59424          // 64 ints
#define SM_MBAR  59680          // 8 B
#define SMEM_BYTES 59904

__device__ __forceinline__ float fsigm(float x) {
    return __fdividef(1.0f, 1.0f + __expf(-x));
}
__device__ __forceinline__ float ftanh(float x) {
    float r; asm("tanh.approx.f32 %0, %1;" : "=f"(r) : "f"(x)); return r;
}
__device__ __forceinline__ unsigned int smem_u32(const void* p) {
    unsigned int a;
    asm("{ .reg .u64 t; cvta.to.shared.u64 t, %1; cvt.u32.u64 %0, t; }"
        : "=r"(a) : "l"(p));
    return a;
}
__device__ __forceinline__ unsigned long long fma2(
    unsigned long long a, unsigned long long b, unsigned long long c) {
    unsigned long long d;
    asm("fma.rn.f32x2 %0, %1, %2, %3;" : "=l"(d) : "l"(a), "l"(b), "l"(c));
    return d;
}
__device__ __forceinline__ unsigned long long lds64(unsigned int a) {
    unsigned long long v;
    asm volatile("ld.shared.b64 %0, [%1];" : "=l"(v) : "r"(a));
    return v;
}
__device__ __forceinline__ void lds_v2b64(unsigned int a,
                                          unsigned long long& x,
                                          unsigned long long& y) {
    asm volatile("ld.shared.v2.b64 {%0, %1}, [%2];" : "=l"(x), "=l"(y) : "r"(a));
}
__device__ __forceinline__ float acc_sum(unsigned long long v) {
    return __uint_as_float((unsigned int)v) + __uint_as_float((unsigned int)(v >> 32));
}

__device__ __forceinline__ void mbar_wait0(unsigned int mbar) {
    unsigned int done;
    asm volatile(
        "{\n\t.reg .pred p;\n\t"
        "mbarrier.try_wait.parity.acquire.cta.shared::cta.b64 p, [%1], 0;\n\t"
        "selp.b32 %0, 1, 0, p;\n\t}"
        : "=r"(done) : "r"(mbar) : "memory");
    if (!done) {
        asm volatile(
            "{\n\t.reg .pred P1;\n\t"
            "WL_%=:\n\t"
            "mbarrier.try_wait.parity.acquire.cta.shared::cta.b64 P1, [%0], 0, 0x989680;\n\t"
            "@P1 bra.uni WD_%=;\n\t"
            "bra.uni WL_%=;\n\t"
            "WD_%=:\n\t}"
            :: "r"(mbar) : "memory");
    }
}

__global__ void __launch_bounds__(256, 1) bilstm_kernel(
    const int*   __restrict__ inputs,   // [B, S]
    const float* __restrict__ weight,   // [VOCAB, EMB]
    const float* __restrict__ Wxf,      // [1024, 128]
    const float* __restrict__ bxf,
    const float* __restrict__ bhf,
    const float* __restrict__ Wxb,
    const float* __restrict__ bxb,
    const float* __restrict__ bhb,
    const float* __restrict__ Why,      // [32, 256]
    const float* __restrict__ by,       // [32]
    float*       __restrict__ out)      // [B, 32]
{
    extern __shared__ char dsm[];
    const int tid = threadIdx.x;
    const int bid = blockIdx.x;

    if (bid < 128) {
        // ================= WORKER =================
        const int hc     = bid & 31;
        const int bg     = bid >> 5;
        const int h_base = hc * 8;
        const int b_base = bg * 32;

        float*        xs2f  = (float*)(dsm + SM_XS2);   // pairs: [(dir*64+k2)*33+lb] as float2
        float*        red   = (float*)(dsm + SM_RED);
        int*          tok_s = (int*)  (dsm + SM_TOK);
        const unsigned int sb   = smem_u32(dsm);
        const unsigned int mbar = sb + SM_MBAR;

        if (tid == 0)
            asm volatile("mbarrier.init.shared.b64 [%0], 1;" :: "r"(mbar) : "memory");
        if (tid < 64) {
            const int dir = tid >> 5;
            const int lb  = tid & 31;
            tok_s[tid] = inputs[(b_base + lb) * NB_S + (dir ? 0 : (NB_S - 1))];
        }
        __syncthreads();

        // Kick off 6 bulk copies: W tile (i,g,o per dir; f skipped), 4 KB each.
        if (tid == 0) {
            asm volatile("mbarrier.arrive.expect_tx.shared.b64 _, [%0], %1;"
                         :: "r"(mbar), "r"(24576u) : "memory");
            const int goff[3] = {0, 512, 768};
            #pragma unroll
            for (int c = 0; c < 6; c++) {
                const float* src = (c >= 3 ? Wxb : Wxf)
                                 + (goff[c % 3] + h_base) * NB_EMB;
                const unsigned int dst = sb + SM_WSM + c * 4096;
                asm volatile(
                    "cp.async.bulk.shared::cluster.global.mbarrier::complete_tx::bytes "
                    "[%0], [%1], %2, [%3];"
                    :: "r"(dst), "l"(src), "r"(4096u), "r"(mbar) : "memory");
            }
        }

        // Gather embeddings into transposed-pair layout (overlaps the DMA).
        #pragma unroll
        for (int it = 0; it < 8; it++) {
            const int idx = tid + it * 256;          // 2048 float4 total
            const int e4  = idx & 31;
            const int lb  = (idx >> 5) & 31;
            const int dir = idx >> 10;
            const int tok = tok_s[dir * 32 + lb];
            const float4 v = ((const float4*)(weight + tok * NB_EMB))[e4];
            ((float2*)(xs2f + ((dir * 64 + 2 * e4) * 33 + lb) * 2))[0] =
                make_float2(v.x, v.y);
            ((float2*)(xs2f + ((dir * 64 + 2 * e4 + 1) * 33 + lb) * 2))[0] =
                make_float2(v.z, v.w);
        }

        const int w   = tid >> 5;      // 8 warps
        const int lb  = tid & 31;      // lane = batch
        const int dir = w >> 2;        // 0 fwd / 1 bwd
        const int hp  = w & 3;         // h-pair index

        // Bias sums (warp-uniform; c=0 => only bx + bh survive). 2 h x 3 gates.
        const float* bx = dir ? bxb : bxf;
        const float* bh = dir ? bhb : bhf;
        float bias[6];
        #pragma unroll
        for (int g = 0; g < 3; g++) {
            const int go = (g == 0 ? 0 : (g == 1 ? 512 : 768));
            #pragma unroll
            for (int j = 0; j < 2; j++) {
                const int h = h_base + 2 * hp + j;
                bias[g * 2 + j] = bx[go + h] + bh[go + h];
            }
        }

        __syncthreads();      // xs2 ready
        mbar_wait0(mbar);     // W tile ready

        // GEMV: 2 h x 3 gates, f32x2 over k. W broadcast LDS.128, x CF LDS.64.
        unsigned int wrow[6];
        #pragma unroll
        for (int g = 0; g < 3; g++)
            #pragma unroll
            for (int j = 0; j < 2; j++)
                wrow[g * 2 + j] = sb + SM_WSM
                                + (((dir * 3 + g) * 8) + 2 * hp + j) * 512;

        const unsigned int xbase = sb + SM_XS2 + ((dir * 64) * 33 + lb) * 8;

        unsigned long long acc[6] = {0ull, 0ull, 0ull, 0ull, 0ull, 0ull};
        #pragma unroll 8
        for (int k4 = 0; k4 < 32; k4++) {
            const unsigned long long xa = lds64(xbase + (2 * k4) * 33 * 8);
            const unsigned long long xb = lds64(xbase + (2 * k4 + 1) * 33 * 8);
            #pragma unroll
            for (int r = 0; r < 6; r++) {
                unsigned long long w01, w23;
                lds_v2b64(wrow[r] + k4 * 16, w01, w23);
                acc[r] = fma2(w01, xa, acc[r]);
                acc[r] = fma2(w23, xb, acc[r]);
            }
        }

        float hyv[2];
        #pragma unroll
        for (int j = 0; j < 2; j++) {
            const float gi = acc_sum(acc[0 * 2 + j]) + bias[0 * 2 + j];
            const float gg = acc_sum(acc[1 * 2 + j]) + bias[1 * 2 + j];
            const float go = acc_sum(acc[2 * 2 + j]) + bias[2 * 2 + j];
            hyv[j] = fsigm(go) * ftanh(fsigm(gi) * ftanh(gg));
        }

        __syncthreads();      // xs2 reads done (red overlays nothing, but order anyway)
        if (dir == 1) {
            red[(2 * hp + 0) * 33 + lb] = hyv[0];
            red[(2 * hp + 1) * 33 + lb] = hyv[1];
        }
        __syncthreads();
        if (dir == 0) {
            #pragma unroll
            for (int j = 0; j < 2; j++) {
                const int hl = 2 * hp + j;
                g_hy[(h_base + hl) * NB_B + b_base + lb] =
                    hyv[j] + red[hl * 33 + lb];
            }
        }

        __syncthreads();
        if (tid == 0) {
            __threadfence();
            atomicAdd(&g_wcnt[bg], 1u);
        }
    } else {
        // ================= HEAD =================
        const int hb = bid - 128;        // 0..31
        const int bg = hb >> 3;
        const int bq = hb & 7;
        const int b0 = bg * 32 + bq * 4;

        float* Why_s = (float*)(dsm + SM_XS2);   // [k*33 + o]
        float* hy_s  = (float*)(dsm + SM_HYS);   // [k*4 + bl]
        float* red2  = (float*)(dsm + SM_RED2);  // [bl*33 + o]

        // Stage Why transposed (overlaps the worker phase).
        #pragma unroll
        for (int it = 0; it < 32; it++) {
            const int idx = tid + it * 256;      // 8192
            const int o = idx >> 8;
            const int k = idx & 255;
            Why_s[k * 33 + o] = Why[idx];
        }

        // Epoch-safe wait: N = hcnt/8 (this block hasn't incremented yet),
        // wait until wcnt >= 32*(N+1).
        if (tid == 0) {
            unsigned int h0;
            asm volatile("ld.global.relaxed.gpu.u32 %0, [%1];"
                         : "=r"(h0) : "l"(&g_hcnt[bg]));
            const unsigned int target = ((h0 >> 3) + 1u) * 32u;
            unsigned int v;
            do {
                asm volatile("ld.global.acquire.gpu.u32 %0, [%1];"
                             : "=r"(v) : "l"(&g_wcnt[bg]) : "memory");
                if ((int)(v - target) >= 0) break;
                __nanosleep(64);
            } while (true);
        }
        __syncthreads();

        // Stage hy for 4 batches: 1024 floats.
        #pragma unroll
        for (int it = 0; it < 4; it++) {
            const int idx = tid + it * 256;
            const int k  = idx >> 2;
            const int bl = idx & 3;
            hy_s[idx] = g_hy[k * NB_B + b0 + bl];
        }
        __syncthreads();

        // warp = (bl, k-half); lane = output o.
        const int o  = tid & 31;
        const int w  = tid >> 5;
        const int bl = w & 3;
        const int kh = w >> 2;
        const int k0 = kh * 128;

        float a0 = 0.f, a1 = 0.f;
        #pragma unroll 8
        for (int k = 0; k < 128; k += 2) {
            a0 = fmaf(hy_s[(k0 + k) * 4 + bl],     Why_s[(k0 + k) * 33 + o],     a0);
            a1 = fmaf(hy_s[(k0 + k + 1) * 4 + bl], Why_s[(k0 + k + 1) * 33 + o], a1);
        }
        const float part = a0 + a1;

        if (kh == 1) red2[bl * 33 + o] = part;
        __syncthreads();
        if (kh == 0) {
            const float acc = part + red2[bl * 33 + o] + by[o];
            float mx = acc;
            #pragma unroll
            for (int off = 16; off; off >>= 1)
                mx = fmaxf(mx, __shfl_xor_sync(0xffffffffu, mx, off));
            float s = __expf(acc - mx);
            #pragma unroll
            for (int off = 16; off; off >>= 1)
                s += __shfl_xor_sync(0xffffffffu, s, off);
            out[(b0 + bl) * NB_OUT + o] = acc - mx - __logf(s);
        }

        __syncthreads();
        if (tid == 0) atomicAdd(&g_hcnt[bg], 1u);
    }
}

// Inputs in metadata order:
// 0 inputs(int32) 1 weight 2 Wxf 3 bxf 4 Whf(unused) 5 bhf
// 6 Wxb 7 bxb 8 Whb(unused) 9 bhb 10 Why 11 by
extern "C" void kernel_launch(void* const* d_in, const int* in_sizes, int n_in,
                              void* d_out, int out_size)
{
    const int*   inputs = (const int*)  d_in[0];
    const float* weight = (const float*)d_in[1];
    const float* Wxf    = (const float*)d_in[2];
    const float* bxf    = (const float*)d_in[3];
    const float* bhf    = (const float*)d_in[5];
    const float* Wxb    = (const float*)d_in[6];
    const float* bxb    = (const float*)d_in[7];
    const float* bhb    = (const float*)d_in[9];
    const float* Why    = (const float*)d_in[10];
    const float* by     = (const float*)d_in[11];
    float*       out    = (float*)d_out;

    static int configured = 0;
    if (!configured) {
        cudaFuncSetAttribute(bilstm_kernel,
                             cudaFuncAttributeMaxDynamicSharedMemorySize,
                             SMEM_BYTES);
        configured = 1;
    }

    bilstm_kernel<<<160, 256, SMEM_BYTES>>>(inputs, weight, Wxf, bxf, bhf,
                                            Wxb, bxb, bhb, Why, by, out);
}